// round 11
// baseline (speedup 1.0000x reference)
#include <cuda_runtime.h>
#include <cuda_bf16.h>
#include <cuda_fp16.h>
#include <cstdint>
#include <cstddef>

// tcgen05 is arch-SPECIFIC (sm_103a / sm_100a). The harness also compiles a
// plain compute_103 pass where tcgen05 is illegal, so gate every tcgen05 use.
#if !defined(__CUDA_ARCH__) || defined(__CUDA_ARCH_FEAT_SM103_ALL) || \
    defined(__CUDA_ARCH_FEAT_SM100_ALL) || defined(__CUDA_ARCH_FEAT_SM101_ALL)
#define TC_OK 1
#else
#define TC_OK 0
#endif

// Problem sizes (exact: B=4096, D=4096, L=32768, k=64)
#define BMAX 4096
#define DMAX 4096
#define LMAX 32768
#define K_MAX 512
#define CAND_MAX 128
#define CAPB 2048
#define DELTA 1e-4f

// ---------------------------------------------------------------------------
// Device-global scratch. Deduped splits; wdt fp16.
// ---------------------------------------------------------------------------
__device__ float          g_xc[(size_t)BMAX * DMAX];          // 64MB
__device__ __half         g_wdt[(size_t)LMAX * DMAX];         // W_dec^T fp16 (256MB)
__device__ unsigned short g_aq[(size_t)BMAX * 2 * DMAX];      // [a1,a2] (64MB)
__device__ unsigned short g_bq[(size_t)LMAX * 2 * DMAX];      // [b1,b2] (512MB)
__device__ int   g_tk_idx[(size_t)BMAX * K_MAX];
__device__ float g_tk_val[(size_t)BMAX * K_MAX];
__device__ int   g_cand_idx[(size_t)BMAX * CAND_MAX];
__device__ int   g_nhi[BMAX];
__device__ int   g_ncand[BMAX];
__device__ int   g_nsel[BMAX];

// ---------------------------------------------------------------------------
// PTX helpers
// ---------------------------------------------------------------------------
__device__ __forceinline__ uint32_t smem_u32(const void* p) {
    uint32_t a;
    asm("{ .reg .u64 t; cvta.to.shared.u64 t, %1; cvt.u32.u64 %0, t; }"
        : "=r"(a) : "l"(p));
    return a;
}

#define MBARRIER_INIT(addr, cnt) \
    asm volatile("mbarrier.init.shared.b64 [%0], %1;" :: "r"(addr), "r"(cnt) : "memory")

#define MBARRIER_ARRIVE(addr) \
    asm volatile("mbarrier.arrive.shared.b64 _, [%0];" :: "r"(addr) : "memory")

#define MBARRIER_WAIT_PARITY(addr, par) do {                                   \
    uint32_t _m = (addr); uint32_t _p = (par); uint32_t _d;                    \
    asm volatile("{\n\t.reg .pred p;\n\t"                                      \
        "mbarrier.try_wait.parity.acquire.cta.shared::cta.b64 p, [%1], %2;\n\t"\
        "selp.b32 %0, 1, 0, p;\n\t}"                                           \
        : "=r"(_d) : "r"(_m), "r"(_p) : "memory");                             \
    if (!_d) {                                                                 \
        asm volatile("{\n\t.reg .pred P1;\n\t"                                 \
            "WL_%=:\n\t"                                                       \
            "mbarrier.try_wait.parity.acquire.cta.shared::cta.b64 P1, [%0], %1, 0x989680;\n\t" \
            "@P1 bra.uni WD_%=;\n\t"                                           \
            "bra.uni WL_%=;\n\t"                                               \
            "WD_%=:\n\t}" :: "r"(_m), "r"(_p) : "memory");                     \
    }                                                                          \
} while (0)

// noinc: arrival counts against the init count (default form self-balances
// and can never complete a phase — R4 hang).
#define CPASYNC_ARRIVE_NOINC(addr) \
    asm volatile("cp.async.mbarrier.arrive.noinc.shared::cta.b64 [%0];" \
                 :: "r"(addr) : "memory")

#if TC_OK
#define TCGEN05_ALLOC(sp, n) \
    asm volatile("tcgen05.alloc.cta_group::1.sync.aligned.shared::cta.b32 [%0], %1;" \
                 :: "r"((uint32_t)(sp)), "r"((uint32_t)(n)) : "memory")
#define TCGEN05_DEALLOC(t, n) \
    asm volatile("tcgen05.dealloc.cta_group::1.sync.aligned.b32 %0, %1;" :: "r"(t), "r"(n))
#define TCGEN05_COMMIT(mb) \
    asm volatile("tcgen05.commit.cta_group::1.mbarrier::arrive::one.shared::cluster.b64 [%0];" \
                 :: "r"((uint32_t)(mb)) : "memory")
#define TCGEN05_WAIT_LD() asm volatile("tcgen05.wait::ld.sync.aligned;" ::: "memory")
#define TCGEN05_FENCE_AFTER() asm volatile("tcgen05.fence::after_thread_sync;" ::: "memory")
#define TCGEN05_FENCE_BEFORE() asm volatile("tcgen05.fence::before_thread_sync;" ::: "memory")
#define FENCE_PROXY_ASYNC() asm volatile("fence.proxy.async.shared::cta;" ::: "memory")

#define TCGEN05_LD_X32(r, ta) \
    asm volatile("tcgen05.ld.sync.aligned.32x32b.x32.b32 " \
        "{%0,%1,%2,%3,%4,%5,%6,%7,%8,%9,%10,%11,%12,%13,%14,%15," \
        "%16,%17,%18,%19,%20,%21,%22,%23,%24,%25,%26,%27,%28,%29,%30,%31}, [%32];" \
        : "=r"((r)[0]),"=r"((r)[1]),"=r"((r)[2]),"=r"((r)[3]), \
          "=r"((r)[4]),"=r"((r)[5]),"=r"((r)[6]),"=r"((r)[7]), \
          "=r"((r)[8]),"=r"((r)[9]),"=r"((r)[10]),"=r"((r)[11]), \
          "=r"((r)[12]),"=r"((r)[13]),"=r"((r)[14]),"=r"((r)[15]), \
          "=r"((r)[16]),"=r"((r)[17]),"=r"((r)[18]),"=r"((r)[19]), \
          "=r"((r)[20]),"=r"((r)[21]),"=r"((r)[22]),"=r"((r)[23]), \
          "=r"((r)[24]),"=r"((r)[25]),"=r"((r)[26]),"=r"((r)[27]), \
          "=r"((r)[28]),"=r"((r)[29]),"=r"((r)[30]),"=r"((r)[31]) \
        : "r"(ta))

// SW128 K-major smem descriptor (version=1, SBO=64, LBO=1, layout=SW128)
__device__ __forceinline__ uint64_t make_desc(uint32_t addr) {
    const uint64_t base = (uint64_t(2) << 61) | (uint64_t(1) << 46) |
                          (uint64_t(64) << 32) | (uint64_t(1) << 16);
    return base | ((uint64_t)(addr >> 4) & 0x3FFF);
}

__device__ __forceinline__ void mma_f16_ss_cg1(
    uint32_t d, uint64_t adesc, uint64_t bdesc, uint32_t idesc, uint32_t en)
{
    asm volatile("{\n\t.reg .pred p;\n\tsetp.ne.u32 p, %5, 0;\n\t"
        "tcgen05.mma.cta_group::1.kind::f16 [%0], %1, %2, %3, {%4,%4,%4,%4}, p;\n\t}"
        :: "r"(d), "l"(adesc), "l"(bdesc), "r"(idesc), "r"(0u), "r"(en) : "memory");
}
#endif // TC_OK

// ---------------------------------------------------------------------------
// Split kernels (deduped): Aq row = [a1, a2], Bq row = [b1, b2]; also xc.
// ---------------------------------------------------------------------------
__global__ __launch_bounds__(256) void split_a_kernel(
    const float* __restrict__ x, const float* __restrict__ pb,
    float* __restrict__ xc, unsigned short* __restrict__ Aq, int D)
{
    int d = blockIdx.x * 256 + threadIdx.x;
    int b = blockIdx.y;
    if (d >= D) return;
    float v = x[(size_t)b * D + d] - pb[d];
    xc[(size_t)b * D + d] = v;
    __nv_bfloat16 h1 = __float2bfloat16_rn(v);
    __nv_bfloat16 h2 = __float2bfloat16_rn(v - __bfloat162float(h1));
    size_t base = (size_t)b * 2 * D;
    Aq[base + d]     = __bfloat16_as_ushort(h1);
    Aq[base + D + d] = __bfloat16_as_ushort(h2);
}

__global__ __launch_bounds__(256) void split_b_kernel(
    const float* __restrict__ W, unsigned short* __restrict__ Bq, int D)
{
    int d = blockIdx.x * 256 + threadIdx.x;
    int l = blockIdx.y;
    if (d >= D) return;
    float v = W[(size_t)l * D + d];
    __nv_bfloat16 h1 = __float2bfloat16_rn(v);
    __nv_bfloat16 h2 = __float2bfloat16_rn(v - __bfloat162float(h1));
    size_t base = (size_t)l * 2 * D;
    Bq[base + d]     = __bfloat16_as_ushort(h1);
    Bq[base + D + d] = __bfloat16_as_ushort(h2);
}

// ---------------------------------------------------------------------------
// W_dec [D,L] -> g_wdt [L,D] in fp16
// ---------------------------------------------------------------------------
__global__ __launch_bounds__(256) void transpose_kernel(
    const float* __restrict__ in, __half* __restrict__ out, int D, int L)
{
    __shared__ float tile[32][33];
    int l0 = blockIdx.x * 32, d0 = blockIdx.y * 32;
    int tx = threadIdx.x, ty = threadIdx.y;
#pragma unroll
    for (int i = 0; i < 32; i += 8)
        tile[ty + i][tx] = in[(size_t)(d0 + ty + i) * L + (l0 + tx)];
    __syncthreads();
#pragma unroll
    for (int i = 0; i < 32; i += 8)
        out[(size_t)(l0 + ty + i) * D + (d0 + tx)] = __float2half_rn(tile[tx][ty + i]);
}

// ---------------------------------------------------------------------------
// PERSISTENT tcgen05 bf16 GEMM, tiles 128x256, TMEM double-buffered (2x256
// cols). Warps: 0-3 producers, warp 4 lane 0 = MMA issue, warps 8-11 =
// epilogue (lane-group = wid%4). Virtual K=3D over deduped [x1,x2] storage.
// ---------------------------------------------------------------------------
#define PSTAGES 3
#define PSTAGE_BYTES 49152               // A 16KB + B 32KB
#define POFF_TMEMPTR 0
#define POFF_FULL    8                   // 3 x 8B
#define POFF_EMPTY   32                  // 3 x 8B
#define POFF_BUFDONE 56                  // 2 x 8B
#define POFF_BUFFREE 72                  // 2 x 8B
#define POFF_STAGE   1024
#define POFF_EPI     (POFF_STAGE + PSTAGES * PSTAGE_BYTES)       // 148480
#define PGEMM_SMEM   (POFF_EPI + 4 * 32 * 33 * 4)                // 165376
#define PIDESC ((1u << 4) | (1u << 7) | (1u << 10) | ((256u / 8) << 17) | ((128u / 16) << 24))

__global__ __launch_bounds__(384, 1) void gemm_kernel(
    const unsigned short* __restrict__ Aq, const unsigned short* __restrict__ Bq,
    const float* __restrict__ bias, float* __restrict__ C,
    int M, int N, int D)
{
#if TC_OK
    extern __shared__ char smem[];
    uint32_t sb = smem_u32(smem);
    int tid = threadIdx.x;
    int wid = tid >> 5;

    int mtiles = M >> 7;                  // 32 (128-row tiles)
    int ntiles = N >> 8;                  // 128 (256-col tiles)
    int ntile_tot = mtiles * ntiles;      // 4096
    int gsz = mtiles * 8;                 // supertile group: 8 nt x all mt
    const int cpp = D >> 6;               // chunks per phase (64)
    const int nchunk = 3 * cpp;           // 192
    const size_t rowstride = (size_t)(2 * D);

    if (tid == 0) {
#pragma unroll
        for (int s = 0; s < PSTAGES; s++) {
            MBARRIER_INIT(sb + POFF_FULL + s * 8, 128);
            MBARRIER_INIT(sb + POFF_EMPTY + s * 8, 1);
        }
#pragma unroll
        for (int p = 0; p < 2; p++) {
            MBARRIER_INIT(sb + POFF_BUFDONE + p * 8, 1);
            MBARRIER_INIT(sb + POFF_BUFFREE + p * 8, 128);
        }
    }
    if (wid == 4) TCGEN05_ALLOC(sb + POFF_TMEMPTR, 512);
    __syncthreads();
    uint32_t tmem;
    asm volatile("ld.shared.b32 %0, [%1];" : "=r"(tmem) : "r"(sb + POFF_TMEMPTR));

    if (tid < 128) {
        // ------------- producers: stream chunks continuously across tiles ---
        int rrA = tid >> 3, cq = tid & 7;
        int cc = 0;
        for (int ti = blockIdx.x; ti < ntile_tot; ti += gridDim.x) {
            int g = ti / gsz, r = ti % gsz;
            int mt = r % mtiles, nt = g * 8 + r / mtiles;
            const unsigned short* Abase = Aq + (size_t)(mt << 7) * rowstride;
            const unsigned short* Bbase = Bq + (size_t)(nt << 8) * rowstride;
            for (int it = 0; it < nchunk; it++, cc++) {
                int s = cc % PSTAGES;
                int u = cc / PSTAGES;
                if (u >= 1)
                    MBARRIER_WAIT_PARITY(sb + POFF_EMPTY + s * 8, (u - 1) & 1);
                int ph = it / cpp, r64 = it % cpp;
                int aoe = ((ph == 2) ? D : 0) + r64 * 64;
                int boe = ((ph == 1) ? D : 0) + r64 * 64;
                uint32_t aoff = sb + POFF_STAGE + s * PSTAGE_BYTES;
                uint32_t boff = aoff + 16384;
                const unsigned short* gA = Abase + aoe + cq * 8;
                const unsigned short* gB = Bbase + boe + cq * 8;
#pragma unroll
                for (int i = 0; i < 8; i++) {              // A: 128 rows
                    int rr = i * 16 + rrA;
                    uint32_t off = rr * 128 + cq * 16;
                    uint32_t sw = off ^ ((off >> 3) & 0x70);
                    asm volatile("cp.async.cg.shared.global [%0], [%1], 16;"
                                 :: "r"(aoff + sw), "l"(gA + (size_t)rr * rowstride) : "memory");
                }
#pragma unroll
                for (int i = 0; i < 16; i++) {             // B: 256 rows
                    int rr = i * 16 + rrA;
                    uint32_t off = rr * 128 + cq * 16;
                    uint32_t sw = off ^ ((off >> 3) & 0x70);
                    asm volatile("cp.async.cg.shared.global [%0], [%1], 16;"
                                 :: "r"(boff + sw), "l"(gB + (size_t)rr * rowstride) : "memory");
                }
                CPASYNC_ARRIVE_NOINC(sb + POFF_FULL + s * 8);
            }
        }
    } else if (tid == 128) {
        // ------------- MMA issue thread -------------------------------------
        int cc = 0, tt = 0;
        for (int ti = blockIdx.x; ti < ntile_tot; ti += gridDim.x, tt++) {
            int p = tt & 1;
            if (tt >= 2)
                MBARRIER_WAIT_PARITY(sb + POFF_BUFFREE + p * 8, ((tt >> 1) - 1) & 1);
            for (int it = 0; it < nchunk; it++, cc++) {
                int s = cc % PSTAGES;
                int u = cc / PSTAGES;
                MBARRIER_WAIT_PARITY(sb + POFF_FULL + s * 8, u & 1);
                FENCE_PROXY_ASYNC();
                uint32_t aoff = sb + POFF_STAGE + s * PSTAGE_BYTES;
                uint32_t boff = aoff + 16384;
                uint64_t adesc = make_desc(aoff);
                uint64_t bdesc = make_desc(boff);
#pragma unroll
                for (int kk = 0; kk < 4; kk++) {
                    uint32_t en = (it == 0 && kk == 0) ? 0u : 1u;
                    mma_f16_ss_cg1(tmem + p * 256, adesc + kk * 2,
                                   bdesc + kk * 2, PIDESC, en);
                }
                TCGEN05_COMMIT(sb + POFF_EMPTY + s * 8);
            }
            TCGEN05_COMMIT(sb + POFF_BUFDONE + p * 8);
        }
    } else if (wid >= 8 && wid < 12) {
        // ------------- epilogue warps: drain buffer p while p^1 computes ----
        int lg = wid - 8;                   // == wid % 4 (SMSP-matched)
        int lid = tid & 31;
        float* ebuf = (float*)(smem + POFF_EPI) + lg * (32 * 33);
        int tt = 0;
        for (int ti = blockIdx.x; ti < ntile_tot; ti += gridDim.x, tt++) {
            int p = tt & 1;
            int g = ti / gsz, r = ti % gsz;
            int mt = r % mtiles, nt = g * 8 + r / mtiles;
            MBARRIER_WAIT_PARITY(sb + POFF_BUFDONE + p * 8, (tt >> 1) & 1);
            TCGEN05_FENCE_AFTER();
            int n0 = nt << 8;
            int rbase = (mt << 7) + lg * 32;
            for (int cb = 0; cb < 8; cb++) {
                uint32_t regs[32];
                TCGEN05_LD_X32(regs, tmem + p * 256 + cb * 32 + (((uint32_t)lg) << 21));
                TCGEN05_WAIT_LD();
#pragma unroll
                for (int j = 0; j < 32; j++) ebuf[lid * 33 + j] = __uint_as_float(regs[j]);
                __syncwarp();
                float bv = bias[n0 + cb * 32 + lid];
#pragma unroll
                for (int rr = 0; rr < 32; rr++) {
                    C[(size_t)(rbase + rr) * N + n0 + cb * 32 + lid] =
                        ebuf[rr * 33 + lid] + bv;
                }
                __syncwarp();
            }
            TCGEN05_FENCE_BEFORE();
            MBARRIER_ARRIVE(sb + POFF_BUFFREE + p * 8);
        }
    }

    __syncthreads();
    if (wid == 4) TCGEN05_DEALLOC(tmem, 512);
#endif // TC_OK
}

// ---------------------------------------------------------------------------
// TopK v2.1: 2-pass, float4 loads, fused latents zero-write (R9 version)
// ---------------------------------------------------------------------------
__device__ __forceinline__ unsigned ord_key(float v) {
    unsigned u = __float_as_uint(v);
    return (u & 0x80000000u) ? ~u : (u | 0x80000000u);
}

__global__ __launch_bounds__(256) void topk_kernel(
    const float* __restrict__ pre, const int* __restrict__ kptr,
    float* __restrict__ latents, int* __restrict__ tki, float* __restrict__ tkv,
    int* __restrict__ cand, int L)
{
    __shared__ int   hist[CAPB];
    __shared__ int   segsum[256];
    __shared__ float s_cv[CAPB];
    __shared__ int   s_ci[CAPB];
    __shared__ int   s_bin, s_c1, s_nbin, s_nhi, s_nc;
    __shared__ unsigned s_vkkey;

    int tid = threadIdx.x;
    int row = blockIdx.x;
    const float4* p4 = (const float4*)(pre + (size_t)row * L);
    float4* lat4 = (float4*)(latents + (size_t)row * L);
    int L4 = L >> 2;

    int k = *kptr;
    if (k > K_MAX) k = K_MAX;
    if (k > L)     k = L;
    if (k <= 0) {
        float4 z = make_float4(0.f, 0.f, 0.f, 0.f);
        for (int i = tid; i < L4; i += 256) lat4[i] = z;
        if (tid == 0) { g_nhi[row] = 0; g_ncand[row] = 0; g_nsel[row] = 0; }
        return;
    }

#pragma unroll
    for (int j = tid; j < CAPB; j += 256) hist[j] = 0;
    __syncthreads();
    for (int i = tid; i < L4; i += 256) {
        float4 v4 = p4[i];
        atomicAdd(&hist[ord_key(v4.x) >> 21], 1);
        atomicAdd(&hist[ord_key(v4.y) >> 21], 1);
        atomicAdd(&hist[ord_key(v4.z) >> 21], 1);
        atomicAdd(&hist[ord_key(v4.w) >> 21], 1);
    }
    __syncthreads();

    {
        int base = tid * 8, s = 0;
#pragma unroll
        for (int j = 0; j < 8; j++) s += hist[base + j];
        segsum[tid] = s;
        __syncthreads();
        for (int off = 1; off < 256; off <<= 1) {
            int v = (tid + off < 256) ? segsum[tid + off] : 0;
            __syncthreads();
            segsum[tid] += v;
            __syncthreads();
        }
        int nxt = (tid < 255) ? segsum[tid + 1] : 0;
        if (nxt < k && segsum[tid] >= k) {
            int running = nxt;
#pragma unroll
            for (int j = 7; j >= 0; j--) {
                int c = hist[base + j];
                if (running < k && running + c >= k) { s_bin = base + j; s_c1 = running; }
                running += c;
            }
        }
    }
    if (tid == 0) { s_nbin = 0; s_nhi = 0; s_nc = 0; }
    __syncthreads();
    int binb = s_bin, c1 = s_c1;
    int rem = k - c1;

    for (int i = tid; i < L4; i += 256) {
        float4 v4 = p4[i];
        float vv[4] = {v4.x, v4.y, v4.z, v4.w};
        float ov[4];
#pragma unroll
        for (int q = 0; q < 4; q++) {
            float v = vv[q];
            int u11 = (int)(ord_key(v) >> 21);
            float rv = v > 0.f ? v : 0.f;
            if (u11 > binb) {
                ov[q] = rv;
                int slot = atomicAdd(&s_nhi, 1);
                if (slot < K_MAX) {
                    tki[(size_t)row * K_MAX + slot] = i * 4 + q;
                    tkv[(size_t)row * K_MAX + slot] = rv;
                }
            } else {
                ov[q] = 0.f;
                if (u11 == binb) {
                    int c = atomicAdd(&s_nbin, 1);
                    if (c < CAPB) { s_cv[c] = v; s_ci[c] = i * 4 + q; }
                }
            }
        }
        lat4[i] = make_float4(ov[0], ov[1], ov[2], ov[3]);
    }
    __syncthreads();
    int nbin = s_nbin < CAPB ? s_nbin : CAPB;
    if (rem > nbin) rem = nbin;

    for (int j = tid; j < nbin; j += 256) {
        unsigned kj = ord_key(s_cv[j]);
        int cgt = 0, ceq = 0;
        for (int i = 0; i < nbin; i++) {
            unsigned ki = ord_key(s_cv[i]);
            cgt += (ki > kj);
            ceq += (ki == kj);
        }
        if (cgt <= rem - 1 && rem - 1 < cgt + ceq) s_vkkey = kj;
    }
    __syncthreads();

    float v_k;
    {
        unsigned kk2 = s_vkkey;
        unsigned u = (kk2 & 0x80000000u) ? (kk2 & 0x7fffffffu) : ~kk2;
        v_k = __uint_as_float(u);
    }
    float w_hi = v_k + DELTA, w_lo = v_k - DELTA;

    for (int j = tid; j < nbin; j += 256) {
        float v = s_cv[j];
        if (v > w_hi) {
            int slot = atomicAdd(&s_nhi, 1);
            if (slot < K_MAX) {
                float rv = v > 0.f ? v : 0.f;
                latents[(size_t)row * L + s_ci[j]] = rv;
                tki[(size_t)row * K_MAX + slot] = s_ci[j];
                tkv[(size_t)row * K_MAX + slot] = rv;
            }
        } else if (v > w_lo) {
            int c = atomicAdd(&s_nc, 1);
            if (c < CAND_MAX)
                cand[(size_t)row * CAND_MAX + c] = s_ci[j];
        }
    }
    __syncthreads();
    if (tid == 0) {
        g_nhi[row]   = s_nhi < K_MAX ? s_nhi : K_MAX;
        g_ncand[row] = s_nc < CAND_MAX ? s_nc : CAND_MAX;
    }
}

// ---------------------------------------------------------------------------
// fp64 boundary refinement (R9 version)
// ---------------------------------------------------------------------------
__global__ __launch_bounds__(256) void refine_kernel(
    const float* __restrict__ xc, const float* __restrict__ W,
    const float* __restrict__ lb, const float* __restrict__ pre,
    const int* __restrict__ kptr,
    float* __restrict__ latents, int* __restrict__ tki, float* __restrict__ tkv,
    const int* __restrict__ cand, int D, int L)
{
    __shared__ double s_val[CAND_MAX];
    __shared__ double s_red[8];
    __shared__ unsigned char s_win[CAND_MAX];

    int row = blockIdx.x, tid = threadIdx.x;
    int k = *kptr;
    if (k > K_MAX) k = K_MAX;
    if (k > L)     k = L;
    if (k <= 0) return;

    int nhi = g_nhi[row];
    int nc  = g_ncand[row];
    int m = k - nhi;
    if (m < 0) m = 0;
    if (m > nc) m = nc;

    if (nc > m) {
        for (int j = 0; j < nc; j++) {
            int idx = cand[(size_t)row * CAND_MAX + j];
            const float* xr = xc + (size_t)row * D;
            const float* wr = W  + (size_t)idx * D;
            double part = 0.0;
            for (int t = tid; t < D; t += 256)
                part += (double)xr[t] * (double)wr[t];
#pragma unroll
            for (int off = 16; off > 0; off >>= 1)
                part += __shfl_down_sync(0xFFFFFFFFu, part, off);
            if ((tid & 31) == 0) s_red[tid >> 5] = part;
            __syncthreads();
            if (tid == 0) {
                double tot = 0.0;
#pragma unroll
                for (int w = 0; w < 8; w++) tot += s_red[w];
                s_val[j] = tot + (double)lb[idx];
            }
            __syncthreads();
        }
        if (tid == 0) {
            for (int j = 0; j < nc; j++) s_win[j] = 0;
            for (int s = 0; s < m; s++) {
                int best = -1; double bv = -1e300;
                for (int j = 0; j < nc; j++)
                    if (!s_win[j] && s_val[j] > bv) { bv = s_val[j]; best = j; }
                if (best >= 0) s_win[best] = 1;
            }
        }
        __syncthreads();
    } else {
        if (tid < CAND_MAX) s_win[tid] = (tid < nc) ? 1 : 0;
        __syncthreads();
    }

    if (tid == 0) {
        int slot = nhi;
        for (int j = 0; j < nc && slot < k; j++) {
            if (s_win[j]) {
                int idx = cand[(size_t)row * CAND_MAX + j];
                float v = pre[(size_t)row * L + idx];
                float rv = v > 0.f ? v : 0.f;
                latents[(size_t)row * L + idx] = rv;
                tki[(size_t)row * K_MAX + slot] = idx;
                tkv[(size_t)row * K_MAX + slot] = rv;
                slot++;
            }
        }
        g_nsel[row] = slot;
    }
}

// ---------------------------------------------------------------------------
// Sparse decode with fp16 weights (half2 loads, fp32 accumulate)
// ---------------------------------------------------------------------------
__global__ __launch_bounds__(256) void decode_kernel(
    const float* __restrict__ pb,
    const int* __restrict__ tki, const float* __restrict__ tkv,
    const __half* __restrict__ wdt, float* __restrict__ out, int D)
{
    __shared__ int   sidx[K_MAX];
    __shared__ float sval[K_MAX];
    int row = blockIdx.x, tid = threadIdx.x;
    int k = g_nsel[row];
    if (k > K_MAX) k = K_MAX;
    for (int i = tid; i < k; i += 256) {
        sidx[i] = tki[(size_t)row * K_MAX + i];
        sval[i] = tkv[(size_t)row * K_MAX + i];
    }
    __syncthreads();

    const int nc2 = D >> 9;
    const float2* pb2 = (const float2*)pb;
    float2 acc[8];
#pragma unroll
    for (int c = 0; c < 8; c++) {
        if (c < nc2) acc[c] = pb2[c * 256 + tid];
        else acc[c] = make_float2(0.f, 0.f);
    }

    for (int j = 0; j < k; j++) {
        float v = sval[j];
        const __half2* w2 = (const __half2*)(wdt + (size_t)sidx[j] * D);
#pragma unroll
        for (int c = 0; c < 8; c++) {
            if (c < nc2) {
                float2 wf = __half22float2(w2[c * 256 + tid]);
                acc[c].x += v * wf.x;
                acc[c].y += v * wf.y;
            }
        }
    }

    float2* o2 = (float2*)(out + (size_t)row * D);
#pragma unroll
    for (int c = 0; c < 8; c++)
        if (c < nc2) o2[c * 256 + tid] = acc[c];
}

// ---------------------------------------------------------------------------
// Launch — R9 schedule: sequential through GEMM; transpose on side stream
// during topk/refine; join before decode.
// ---------------------------------------------------------------------------
extern "C" void kernel_launch(void* const* d_in, const int* in_sizes, int n_in,
                              void* d_out, int out_size)
{
    const float* x           = (const float*)d_in[0];
    const float* W_enc       = (const float*)d_in[1];
    const float* latent_bias = (const float*)d_in[2];
    const float* pre_bias    = (const float*)d_in[3];
    const float* W_dec       = (const float*)d_in[4];
    const int*   kptr        = (const int*)d_in[5];

    int L = in_sizes[2];
    int D = in_sizes[3];
    int B = in_sizes[0] / D;

    float* out_pre = (float*)d_out;
    float* out_lat = out_pre + (size_t)B * L;
    float* out_rec = out_lat + (size_t)B * L;

    float *xc, *tkv;
    __half* wdt;
    int *tki, *cand;
    unsigned short *aq, *bq;
    cudaGetSymbolAddress((void**)&xc,   g_xc);
    cudaGetSymbolAddress((void**)&wdt,  g_wdt);
    cudaGetSymbolAddress((void**)&tki,  g_tk_idx);
    cudaGetSymbolAddress((void**)&tkv,  g_tk_val);
    cudaGetSymbolAddress((void**)&cand, g_cand_idx);
    cudaGetSymbolAddress((void**)&aq,   g_aq);
    cudaGetSymbolAddress((void**)&bq,   g_bq);

    static cudaStream_t s2 = nullptr;
    static cudaEvent_t evFork = nullptr, evJoin = nullptr;
    static int nsm = 0;
    if (s2 == nullptr) {
        cudaStreamCreateWithFlags(&s2, cudaStreamNonBlocking);
        cudaEventCreateWithFlags(&evFork, cudaEventDisableTiming);
        cudaEventCreateWithFlags(&evJoin, cudaEventDisableTiming);
        cudaDeviceGetAttribute(&nsm, cudaDevAttrMultiProcessorCount, 0);
        if (nsm <= 0) nsm = 148;
    }

    // 1. splits (deduped layouts; also produce xc)
    split_a_kernel<<<dim3((D + 255) / 256, B), 256>>>(x, pre_bias, xc, aq, D);
    split_b_kernel<<<dim3((D + 255) / 256, L), 256>>>(W_enc, bq, D);

    // 2. persistent encode GEMM on tcgen05
    cudaFuncSetAttribute(gemm_kernel, cudaFuncAttributeMaxDynamicSharedMemorySize,
                         PGEMM_SMEM);
    int ntile_tot = (B >> 7) * (L >> 8);
    int grid = nsm < ntile_tot ? nsm : ntile_tot;
    gemm_kernel<<<grid, 384, PGEMM_SMEM>>>(aq, bq, latent_bias, out_pre, B, L, D);

    // 3. fork: transpose W_dec (fp16) on side stream (starts after gemm)
    cudaEventRecord(evFork, 0);
    cudaStreamWaitEvent(s2, evFork, 0);
    transpose_kernel<<<dim3(L / 32, D / 32), dim3(32, 8), 0, s2>>>(W_dec, wdt, D, L);
    cudaEventRecord(evJoin, s2);

    // 4. topk (fused zero-write) + fp64 boundary refine on main stream
    topk_kernel<<<B, 256>>>(out_pre, kptr, out_lat, tki, tkv, cand, L);
    refine_kernel<<<B, 256>>>(xc, W_enc, latent_bias, out_pre, kptr,
                              out_lat, tki, tkv, cand, D, L);

    // 5. join, then sparse decode (fp16 weights)
    cudaStreamWaitEvent(0, evJoin, 0);
    decode_kernel<<<B, 256>>>(pre_bias, tki, tkv, wdt, out_rec, D);
}

// round 12
// speedup vs baseline: 1.2577x; 1.2577x over previous
#include <cuda_runtime.h>
#include <cuda_bf16.h>
#include <cuda_fp16.h>
#include <cstdint>
#include <cstddef>

// tcgen05 is arch-SPECIFIC (sm_103a / sm_100a). The harness also compiles a
// plain compute_103 pass where tcgen05 is illegal, so gate every tcgen05 use.
#if !defined(__CUDA_ARCH__) || defined(__CUDA_ARCH_FEAT_SM103_ALL) || \
    defined(__CUDA_ARCH_FEAT_SM100_ALL) || defined(__CUDA_ARCH_FEAT_SM101_ALL)
#define TC_OK 1
#else
#define TC_OK 0
#endif

// Problem sizes (exact: B=4096, D=4096, L=32768, k=64)
#define BMAX 4096
#define DMAX 4096
#define LMAX 32768
#define K_MAX 512
#define CAND_MAX 128
#define CAPB 2048
#define DELTA 1e-4f

// ---------------------------------------------------------------------------
// Device-global scratch. Deduped splits; wdt fp16. (xc removed in R12 —
// refine recomputes x - pre_bias on the fly, bit-identical fp32.)
// ---------------------------------------------------------------------------
__device__ __half         g_wdt[(size_t)LMAX * DMAX];         // W_dec^T fp16 (256MB)
__device__ unsigned short g_aq[(size_t)BMAX * 2 * DMAX];      // [a1,a2] (64MB)
__device__ unsigned short g_bq[(size_t)LMAX * 2 * DMAX];      // [b1,b2] (512MB)
__device__ int   g_tk_idx[(size_t)BMAX * K_MAX];
__device__ float g_tk_val[(size_t)BMAX * K_MAX];
__device__ int   g_cand_idx[(size_t)BMAX * CAND_MAX];
__device__ int   g_nhi[BMAX];
__device__ int   g_ncand[BMAX];
__device__ int   g_nsel[BMAX];

// ---------------------------------------------------------------------------
// PTX helpers
// ---------------------------------------------------------------------------
__device__ __forceinline__ uint32_t smem_u32(const void* p) {
    uint32_t a;
    asm("{ .reg .u64 t; cvta.to.shared.u64 t, %1; cvt.u32.u64 %0, t; }"
        : "=r"(a) : "l"(p));
    return a;
}

#define MBARRIER_INIT(addr, cnt) \
    asm volatile("mbarrier.init.shared.b64 [%0], %1;" :: "r"(addr), "r"(cnt) : "memory")

#define MBARRIER_WAIT_PARITY(addr, par) do {                                   \
    uint32_t _m = (addr); uint32_t _p = (par); uint32_t _d;                    \
    asm volatile("{\n\t.reg .pred p;\n\t"                                      \
        "mbarrier.try_wait.parity.acquire.cta.shared::cta.b64 p, [%1], %2;\n\t"\
        "selp.b32 %0, 1, 0, p;\n\t}"                                           \
        : "=r"(_d) : "r"(_m), "r"(_p) : "memory");                             \
    if (!_d) {                                                                 \
        asm volatile("{\n\t.reg .pred P1;\n\t"                                 \
            "WL_%=:\n\t"                                                       \
            "mbarrier.try_wait.parity.acquire.cta.shared::cta.b64 P1, [%0], %1, 0x989680;\n\t" \
            "@P1 bra.uni WD_%=;\n\t"                                           \
            "bra.uni WL_%=;\n\t"                                               \
            "WD_%=:\n\t}" :: "r"(_m), "r"(_p) : "memory");                     \
    }                                                                          \
} while (0)

// noinc: arrival counts against the init count (default form self-balances
// and can never complete a phase — R4 hang).
#define CPASYNC_ARRIVE_NOINC(addr) \
    asm volatile("cp.async.mbarrier.arrive.noinc.shared::cta.b64 [%0];" \
                 :: "r"(addr) : "memory")

#if TC_OK
#define TCGEN05_ALLOC(sp, n) \
    asm volatile("tcgen05.alloc.cta_group::1.sync.aligned.shared::cta.b32 [%0], %1;" \
                 :: "r"((uint32_t)(sp)), "r"((uint32_t)(n)) : "memory")
#define TCGEN05_DEALLOC(t, n) \
    asm volatile("tcgen05.dealloc.cta_group::1.sync.aligned.b32 %0, %1;" :: "r"(t), "r"(n))
#define TCGEN05_COMMIT(mb) \
    asm volatile("tcgen05.commit.cta_group::1.mbarrier::arrive::one.shared::cluster.b64 [%0];" \
                 :: "r"((uint32_t)(mb)) : "memory")
#define TCGEN05_WAIT_LD() asm volatile("tcgen05.wait::ld.sync.aligned;" ::: "memory")
#define TCGEN05_FENCE_AFTER() asm volatile("tcgen05.fence::after_thread_sync;" ::: "memory")
#define FENCE_PROXY_ASYNC() asm volatile("fence.proxy.async.shared::cta;" ::: "memory")

#define TCGEN05_LD_X32(r, ta) \
    asm volatile("tcgen05.ld.sync.aligned.32x32b.x32.b32 " \
        "{%0,%1,%2,%3,%4,%5,%6,%7,%8,%9,%10,%11,%12,%13,%14,%15," \
        "%16,%17,%18,%19,%20,%21,%22,%23,%24,%25,%26,%27,%28,%29,%30,%31}, [%32];" \
        : "=r"((r)[0]),"=r"((r)[1]),"=r"((r)[2]),"=r"((r)[3]), \
          "=r"((r)[4]),"=r"((r)[5]),"=r"((r)[6]),"=r"((r)[7]), \
          "=r"((r)[8]),"=r"((r)[9]),"=r"((r)[10]),"=r"((r)[11]), \
          "=r"((r)[12]),"=r"((r)[13]),"=r"((r)[14]),"=r"((r)[15]), \
          "=r"((r)[16]),"=r"((r)[17]),"=r"((r)[18]),"=r"((r)[19]), \
          "=r"((r)[20]),"=r"((r)[21]),"=r"((r)[22]),"=r"((r)[23]), \
          "=r"((r)[24]),"=r"((r)[25]),"=r"((r)[26]),"=r"((r)[27]), \
          "=r"((r)[28]),"=r"((r)[29]),"=r"((r)[30]),"=r"((r)[31]) \
        : "r"(ta))

// SW128 K-major smem descriptor (version=1, SBO=64, LBO=1, layout=SW128)
__device__ __forceinline__ uint64_t make_desc(uint32_t addr) {
    const uint64_t base = (uint64_t(2) << 61) | (uint64_t(1) << 46) |
                          (uint64_t(64) << 32) | (uint64_t(1) << 16);
    return base | ((uint64_t)(addr >> 4) & 0x3FFF);
}

__device__ __forceinline__ void mma_f16_ss_cg1(
    uint32_t d, uint64_t adesc, uint64_t bdesc, uint32_t idesc, uint32_t en)
{
    asm volatile("{\n\t.reg .pred p;\n\tsetp.ne.u32 p, %5, 0;\n\t"
        "tcgen05.mma.cta_group::1.kind::f16 [%0], %1, %2, %3, {%4,%4,%4,%4}, p;\n\t}"
        :: "r"(d), "l"(adesc), "l"(bdesc), "r"(idesc), "r"(0u), "r"(en) : "memory");
}
#endif // TC_OK

// ---------------------------------------------------------------------------
// Split kernels (deduped, float4-vectorized): Aq row = [a1,a2], Bq = [b1,b2].
// ---------------------------------------------------------------------------
__global__ __launch_bounds__(256) void split_a_kernel(
    const float* __restrict__ x, const float* __restrict__ pb,
    unsigned short* __restrict__ Aq, int D)
{
    int d4 = blockIdx.x * 256 + threadIdx.x;        // float4 index
    int b = blockIdx.y;
    if (d4 >= (D >> 2)) return;
    float4 xv = ((const float4*)(x + (size_t)b * D))[d4];
    float4 pv = ((const float4*)pb)[d4];
    float v[4] = {xv.x - pv.x, xv.y - pv.y, xv.z - pv.z, xv.w - pv.w};
    ushort4 u1, u2;
    unsigned short* p1 = (unsigned short*)&u1;
    unsigned short* p2 = (unsigned short*)&u2;
#pragma unroll
    for (int q = 0; q < 4; q++) {
        __nv_bfloat16 h1 = __float2bfloat16_rn(v[q]);
        __nv_bfloat16 h2 = __float2bfloat16_rn(v[q] - __bfloat162float(h1));
        p1[q] = __bfloat16_as_ushort(h1);
        p2[q] = __bfloat16_as_ushort(h2);
    }
    size_t base = (size_t)b * 2 * D;
    ((ushort4*)(Aq + base))[d4]     = u1;
    ((ushort4*)(Aq + base + D))[d4] = u2;
}

__global__ __launch_bounds__(256) void split_b_kernel(
    const float* __restrict__ W, unsigned short* __restrict__ Bq, int D)
{
    int d4 = blockIdx.x * 256 + threadIdx.x;
    int l = blockIdx.y;
    if (d4 >= (D >> 2)) return;
    float4 wv = ((const float4*)(W + (size_t)l * D))[d4];
    float v[4] = {wv.x, wv.y, wv.z, wv.w};
    ushort4 u1, u2;
    unsigned short* p1 = (unsigned short*)&u1;
    unsigned short* p2 = (unsigned short*)&u2;
#pragma unroll
    for (int q = 0; q < 4; q++) {
        __nv_bfloat16 h1 = __float2bfloat16_rn(v[q]);
        __nv_bfloat16 h2 = __float2bfloat16_rn(v[q] - __bfloat162float(h1));
        p1[q] = __bfloat16_as_ushort(h1);
        p2[q] = __bfloat16_as_ushort(h2);
    }
    size_t base = (size_t)l * 2 * D;
    ((ushort4*)(Bq + base))[d4]     = u1;
    ((ushort4*)(Bq + base + D))[d4] = u2;
}

// ---------------------------------------------------------------------------
// W_dec [D,L] -> g_wdt [L,D] in fp16
// ---------------------------------------------------------------------------
__global__ __launch_bounds__(256) void transpose_kernel(
    const float* __restrict__ in, __half* __restrict__ out, int D, int L)
{
    __shared__ float tile[32][33];
    int l0 = blockIdx.x * 32, d0 = blockIdx.y * 32;
    int tx = threadIdx.x, ty = threadIdx.y;
#pragma unroll
    for (int i = 0; i < 32; i += 8)
        tile[ty + i][tx] = in[(size_t)(d0 + ty + i) * L + (l0 + tx)];
    __syncthreads();
#pragma unroll
    for (int i = 0; i < 32; i += 8)
        out[(size_t)(l0 + ty + i) * D + (d0 + tx)] = __float2half_rn(tile[tx][ty + i]);
}

// ---------------------------------------------------------------------------
// tcgen05 bf16 GEMM (R9 exact: 256x256 tiles, 3-stage, virtual K=3D)
// ---------------------------------------------------------------------------
#define GSTAGES 3
#define STAGE_BYTES 65536
#define OFF_TMEMPTR 0
#define OFF_FULL    8
#define OFF_EMPTY   32
#define OFF_DONE    56
#define OFF_STAGE   1024
#define GEMM_SMEM   (OFF_STAGE + GSTAGES * STAGE_BYTES)
#define GIDESC ((1u << 4) | (1u << 7) | (1u << 10) | ((256u / 8) << 17) | ((128u / 16) << 24))

__global__ __launch_bounds__(160, 1) void gemm_kernel(
    const unsigned short* __restrict__ Aq, const unsigned short* __restrict__ Bq,
    const float* __restrict__ bias, float* __restrict__ C,
    int M, int N, int D)
{
#if TC_OK
    extern __shared__ char smem[];
    uint32_t sb = smem_u32(smem);
    int tid = threadIdx.x;
    int wid = tid >> 5;

    int mtiles = M >> 8;
    int bid = blockIdx.x;
    int gsz = mtiles * 8;
    int g = bid / gsz, r = bid % gsz;
    int mt = r % mtiles;
    int nt = g * 8 + r / mtiles;
    int m0 = mt << 8, n0 = nt << 8;

    if (tid == 0) {
#pragma unroll
        for (int s = 0; s < GSTAGES; s++) {
            MBARRIER_INIT(sb + OFF_FULL + s * 8, 128);
            MBARRIER_INIT(sb + OFF_EMPTY + s * 8, 1);
        }
        MBARRIER_INIT(sb + OFF_DONE, 1);
    }
    if (wid == 4) TCGEN05_ALLOC(sb + OFF_TMEMPTR, 512);
    __syncthreads();
    uint32_t tmem;
    asm volatile("ld.shared.b32 %0, [%1];" : "=r"(tmem) : "r"(sb + OFF_TMEMPTR));

    const int cpp = D >> 6;
    const int nchunk = 3 * cpp;
    const size_t rowstride = (size_t)(2 * D);

    if (tid < 128) {
        int rrA = tid >> 3, cq = tid & 7;
        for (int it = 0; it < nchunk; it++) {
            int s = it % GSTAGES;
            int wrap = it / GSTAGES;
            if (it >= GSTAGES)
                MBARRIER_WAIT_PARITY(sb + OFF_EMPTY + s * 8, (wrap - 1) & 1);
            int ph = it / cpp, r64 = it % cpp;
            int aoe = ((ph == 2) ? D : 0) + r64 * 64;
            int boe = ((ph == 1) ? D : 0) + r64 * 64;
            uint32_t aoff = sb + OFF_STAGE + s * STAGE_BYTES;
            uint32_t boff = aoff + 32768;
            const unsigned short* gA = Aq + (size_t)m0 * rowstride + aoe + cq * 8;
            const unsigned short* gB = Bq + (size_t)n0 * rowstride + boe + cq * 8;
#pragma unroll
            for (int i = 0; i < 16; i++) {
                int rr = i * 16 + rrA;
                uint32_t off = rr * 128 + cq * 16;
                uint32_t sw = off ^ ((off >> 3) & 0x70);
                asm volatile("cp.async.cg.shared.global [%0], [%1], 16;"
                             :: "r"(aoff + sw), "l"(gA + (size_t)rr * rowstride) : "memory");
            }
#pragma unroll
            for (int i = 0; i < 16; i++) {
                int rr = i * 16 + rrA;
                uint32_t off = rr * 128 + cq * 16;
                uint32_t sw = off ^ ((off >> 3) & 0x70);
                asm volatile("cp.async.cg.shared.global [%0], [%1], 16;"
                             :: "r"(boff + sw), "l"(gB + (size_t)rr * rowstride) : "memory");
            }
            CPASYNC_ARRIVE_NOINC(sb + OFF_FULL + s * 8);
        }
    } else if (tid == 128) {
        for (int it = 0; it < nchunk; it++) {
            int s = it % GSTAGES;
            int wrap = it / GSTAGES;
            MBARRIER_WAIT_PARITY(sb + OFF_FULL + s * 8, wrap & 1);
            FENCE_PROXY_ASYNC();
            uint32_t aoff = sb + OFF_STAGE + s * STAGE_BYTES;
            uint32_t boff = aoff + 32768;
            uint64_t adesc = make_desc(aoff);
            uint64_t bdesc = make_desc(boff);
#pragma unroll
            for (int kk = 0; kk < 4; kk++) {
                uint32_t en = (it == 0 && kk == 0) ? 0u : 1u;
#pragma unroll
                for (int mh = 0; mh < 2; mh++) {
                    mma_f16_ss_cg1(tmem + mh * 256,
                                   adesc + mh * 1024 + kk * 2,
                                   bdesc + kk * 2, GIDESC, en);
                }
            }
            TCGEN05_COMMIT(sb + OFF_EMPTY + s * 8);
        }
        TCGEN05_COMMIT(sb + OFF_DONE);
    }

    if (tid < 128) {
        MBARRIER_WAIT_PARITY(sb + OFF_DONE, 0);
        TCGEN05_FENCE_AFTER();
        int w = wid, lid = tid & 31;
        float* ebuf = (float*)(smem + OFF_STAGE) + w * (32 * 33);
        uint32_t woff = ((uint32_t)w) << 21;
#pragma unroll
        for (int mh = 0; mh < 2; mh++) {
            for (int cb = 0; cb < 8; cb++) {
                uint32_t regs[32];
                TCGEN05_LD_X32(regs, tmem + mh * 256 + cb * 32 + woff);
                TCGEN05_WAIT_LD();
#pragma unroll
                for (int j = 0; j < 32; j++) ebuf[lid * 33 + j] = __uint_as_float(regs[j]);
                __syncwarp();
                float bv = bias[n0 + cb * 32 + lid];
                int rbase = m0 + mh * 128 + w * 32;
#pragma unroll
                for (int rr = 0; rr < 32; rr++) {
                    C[(size_t)(rbase + rr) * N + n0 + cb * 32 + lid] =
                        ebuf[rr * 33 + lid] + bv;
                }
                __syncwarp();
            }
        }
    }
    __syncthreads();
    if (wid == 4) TCGEN05_DEALLOC(tmem, 512);
#endif // TC_OK
}

// ---------------------------------------------------------------------------
// TopK v2.1: 2-pass, float4 loads, fused latents zero-write (R9 exact)
// ---------------------------------------------------------------------------
__device__ __forceinline__ unsigned ord_key(float v) {
    unsigned u = __float_as_uint(v);
    return (u & 0x80000000u) ? ~u : (u | 0x80000000u);
}

__global__ __launch_bounds__(256) void topk_kernel(
    const float* __restrict__ pre, const int* __restrict__ kptr,
    float* __restrict__ latents, int* __restrict__ tki, float* __restrict__ tkv,
    int* __restrict__ cand, int L)
{
    __shared__ int   hist[CAPB];
    __shared__ int   segsum[256];
    __shared__ float s_cv[CAPB];
    __shared__ int   s_ci[CAPB];
    __shared__ int   s_bin, s_c1, s_nbin, s_nhi, s_nc;
    __shared__ unsigned s_vkkey;

    int tid = threadIdx.x;
    int row = blockIdx.x;
    const float4* p4 = (const float4*)(pre + (size_t)row * L);
    float4* lat4 = (float4*)(latents + (size_t)row * L);
    int L4 = L >> 2;

    int k = *kptr;
    if (k > K_MAX) k = K_MAX;
    if (k > L)     k = L;
    if (k <= 0) {
        float4 z = make_float4(0.f, 0.f, 0.f, 0.f);
        for (int i = tid; i < L4; i += 256) lat4[i] = z;
        if (tid == 0) { g_nhi[row] = 0; g_ncand[row] = 0; g_nsel[row] = 0; }
        return;
    }

#pragma unroll
    for (int j = tid; j < CAPB; j += 256) hist[j] = 0;
    __syncthreads();
    for (int i = tid; i < L4; i += 256) {
        float4 v4 = p4[i];
        atomicAdd(&hist[ord_key(v4.x) >> 21], 1);
        atomicAdd(&hist[ord_key(v4.y) >> 21], 1);
        atomicAdd(&hist[ord_key(v4.z) >> 21], 1);
        atomicAdd(&hist[ord_key(v4.w) >> 21], 1);
    }
    __syncthreads();

    {
        int base = tid * 8, s = 0;
#pragma unroll
        for (int j = 0; j < 8; j++) s += hist[base + j];
        segsum[tid] = s;
        __syncthreads();
        for (int off = 1; off < 256; off <<= 1) {
            int v = (tid + off < 256) ? segsum[tid + off] : 0;
            __syncthreads();
            segsum[tid] += v;
            __syncthreads();
        }
        int nxt = (tid < 255) ? segsum[tid + 1] : 0;
        if (nxt < k && segsum[tid] >= k) {
            int running = nxt;
#pragma unroll
            for (int j = 7; j >= 0; j--) {
                int c = hist[base + j];
                if (running < k && running + c >= k) { s_bin = base + j; s_c1 = running; }
                running += c;
            }
        }
    }
    if (tid == 0) { s_nbin = 0; s_nhi = 0; s_nc = 0; }
    __syncthreads();
    int binb = s_bin, c1 = s_c1;
    int rem = k - c1;

    for (int i = tid; i < L4; i += 256) {
        float4 v4 = p4[i];
        float vv[4] = {v4.x, v4.y, v4.z, v4.w};
        float ov[4];
#pragma unroll
        for (int q = 0; q < 4; q++) {
            float v = vv[q];
            int u11 = (int)(ord_key(v) >> 21);
            float rv = v > 0.f ? v : 0.f;
            if (u11 > binb) {
                ov[q] = rv;
                int slot = atomicAdd(&s_nhi, 1);
                if (slot < K_MAX) {
                    tki[(size_t)row * K_MAX + slot] = i * 4 + q;
                    tkv[(size_t)row * K_MAX + slot] = rv;
                }
            } else {
                ov[q] = 0.f;
                if (u11 == binb) {
                    int c = atomicAdd(&s_nbin, 1);
                    if (c < CAPB) { s_cv[c] = v; s_ci[c] = i * 4 + q; }
                }
            }
        }
        lat4[i] = make_float4(ov[0], ov[1], ov[2], ov[3]);
    }
    __syncthreads();
    int nbin = s_nbin < CAPB ? s_nbin : CAPB;
    if (rem > nbin) rem = nbin;

    for (int j = tid; j < nbin; j += 256) {
        unsigned kj = ord_key(s_cv[j]);
        int cgt = 0, ceq = 0;
        for (int i = 0; i < nbin; i++) {
            unsigned ki = ord_key(s_cv[i]);
            cgt += (ki > kj);
            ceq += (ki == kj);
        }
        if (cgt <= rem - 1 && rem - 1 < cgt + ceq) s_vkkey = kj;
    }
    __syncthreads();

    float v_k;
    {
        unsigned kk2 = s_vkkey;
        unsigned u = (kk2 & 0x80000000u) ? (kk2 & 0x7fffffffu) : ~kk2;
        v_k = __uint_as_float(u);
    }
    float w_hi = v_k + DELTA, w_lo = v_k - DELTA;

    for (int j = tid; j < nbin; j += 256) {
        float v = s_cv[j];
        if (v > w_hi) {
            int slot = atomicAdd(&s_nhi, 1);
            if (slot < K_MAX) {
                float rv = v > 0.f ? v : 0.f;
                latents[(size_t)row * L + s_ci[j]] = rv;
                tki[(size_t)row * K_MAX + slot] = s_ci[j];
                tkv[(size_t)row * K_MAX + slot] = rv;
            }
        } else if (v > w_lo) {
            int c = atomicAdd(&s_nc, 1);
            if (c < CAND_MAX)
                cand[(size_t)row * CAND_MAX + c] = s_ci[j];
        }
    }
    __syncthreads();
    if (tid == 0) {
        g_nhi[row]   = s_nhi < K_MAX ? s_nhi : K_MAX;
        g_ncand[row] = s_nc < CAND_MAX ? s_nc : CAND_MAX;
    }
}

// ---------------------------------------------------------------------------
// fp64 boundary refinement — xc recomputed inline as fp32 (x - pb), identical
// to the value split_a used to store.
// ---------------------------------------------------------------------------
__global__ __launch_bounds__(256) void refine_kernel(
    const float* __restrict__ x, const float* __restrict__ pb,
    const float* __restrict__ W,
    const float* __restrict__ lb, const float* __restrict__ pre,
    const int* __restrict__ kptr,
    float* __restrict__ latents, int* __restrict__ tki, float* __restrict__ tkv,
    const int* __restrict__ cand, int D, int L)
{
    __shared__ double s_val[CAND_MAX];
    __shared__ double s_red[8];
    __shared__ unsigned char s_win[CAND_MAX];

    int row = blockIdx.x, tid = threadIdx.x;
    int k = *kptr;
    if (k > K_MAX) k = K_MAX;
    if (k > L)     k = L;
    if (k <= 0) return;

    int nhi = g_nhi[row];
    int nc  = g_ncand[row];
    int m = k - nhi;
    if (m < 0) m = 0;
    if (m > nc) m = nc;

    if (nc > m) {
        for (int j = 0; j < nc; j++) {
            int idx = cand[(size_t)row * CAND_MAX + j];
            const float* xr = x + (size_t)row * D;
            const float* wr = W + (size_t)idx * D;
            double part = 0.0;
            for (int t = tid; t < D; t += 256) {
                float xct = xr[t] - pb[t];          // fp32, bit-identical to old xc
                part += (double)xct * (double)wr[t];
            }
#pragma unroll
            for (int off = 16; off > 0; off >>= 1)
                part += __shfl_down_sync(0xFFFFFFFFu, part, off);
            if ((tid & 31) == 0) s_red[tid >> 5] = part;
            __syncthreads();
            if (tid == 0) {
                double tot = 0.0;
#pragma unroll
                for (int w = 0; w < 8; w++) tot += s_red[w];
                s_val[j] = tot + (double)lb[idx];
            }
            __syncthreads();
        }
        if (tid == 0) {
            for (int j = 0; j < nc; j++) s_win[j] = 0;
            for (int s = 0; s < m; s++) {
                int best = -1; double bv = -1e300;
                for (int j = 0; j < nc; j++)
                    if (!s_win[j] && s_val[j] > bv) { bv = s_val[j]; best = j; }
                if (best >= 0) s_win[best] = 1;
            }
        }
        __syncthreads();
    } else {
        if (tid < CAND_MAX) s_win[tid] = (tid < nc) ? 1 : 0;
        __syncthreads();
    }

    if (tid == 0) {
        int slot = nhi;
        for (int j = 0; j < nc && slot < k; j++) {
            if (s_win[j]) {
                int idx = cand[(size_t)row * CAND_MAX + j];
                float v = pre[(size_t)row * L + idx];
                float rv = v > 0.f ? v : 0.f;
                latents[(size_t)row * L + idx] = rv;
                tki[(size_t)row * K_MAX + slot] = idx;
                tkv[(size_t)row * K_MAX + slot] = rv;
                slot++;
            }
        }
        g_nsel[row] = slot;
    }
}

// ---------------------------------------------------------------------------
// Sparse decode with fp16 weights (half2 loads, fp32 accumulate) — R9 exact
// ---------------------------------------------------------------------------
__global__ __launch_bounds__(256) void decode_kernel(
    const float* __restrict__ pb,
    const int* __restrict__ tki, const float* __restrict__ tkv,
    const __half* __restrict__ wdt, float* __restrict__ out, int D)
{
    __shared__ int   sidx[K_MAX];
    __shared__ float sval[K_MAX];
    int row = blockIdx.x, tid = threadIdx.x;
    int k = g_nsel[row];
    if (k > K_MAX) k = K_MAX;
    for (int i = tid; i < k; i += 256) {
        sidx[i] = tki[(size_t)row * K_MAX + i];
        sval[i] = tkv[(size_t)row * K_MAX + i];
    }
    __syncthreads();

    const int nc2 = D >> 9;
    const float2* pb2 = (const float2*)pb;
    float2 acc[8];
#pragma unroll
    for (int c = 0; c < 8; c++) {
        if (c < nc2) acc[c] = pb2[c * 256 + tid];
        else acc[c] = make_float2(0.f, 0.f);
    }

    for (int j = 0; j < k; j++) {
        float v = sval[j];
        const __half2* w2 = (const __half2*)(wdt + (size_t)sidx[j] * D);
#pragma unroll
        for (int c = 0; c < 8; c++) {
            if (c < nc2) {
                float2 wf = __half22float2(w2[c * 256 + tid]);
                acc[c].x += v * wf.x;
                acc[c].y += v * wf.y;
            }
        }
    }

    float2* o2 = (float2*)(out + (size_t)row * D);
#pragma unroll
    for (int c = 0; c < 8; c++)
        if (c < nc2) o2[c * 256 + tid] = acc[c];
}

// ---------------------------------------------------------------------------
// Launch — R9 schedule: sequential through GEMM; transpose on side stream
// during topk/refine; join before decode.
// ---------------------------------------------------------------------------
extern "C" void kernel_launch(void* const* d_in, const int* in_sizes, int n_in,
                              void* d_out, int out_size)
{
    const float* x           = (const float*)d_in[0];
    const float* W_enc       = (const float*)d_in[1];
    const float* latent_bias = (const float*)d_in[2];
    const float* pre_bias    = (const float*)d_in[3];
    const float* W_dec       = (const float*)d_in[4];
    const int*   kptr        = (const int*)d_in[5];

    int L = in_sizes[2];
    int D = in_sizes[3];
    int B = in_sizes[0] / D;

    float* out_pre = (float*)d_out;
    float* out_lat = out_pre + (size_t)B * L;
    float* out_rec = out_lat + (size_t)B * L;

    float *tkv;
    __half* wdt;
    int *tki, *cand;
    unsigned short *aq, *bq;
    cudaGetSymbolAddress((void**)&wdt,  g_wdt);
    cudaGetSymbolAddress((void**)&tki,  g_tk_idx);
    cudaGetSymbolAddress((void**)&tkv,  g_tk_val);
    cudaGetSymbolAddress((void**)&cand, g_cand_idx);
    cudaGetSymbolAddress((void**)&aq,   g_aq);
    cudaGetSymbolAddress((void**)&bq,   g_bq);

    static cudaStream_t s2 = nullptr;
    static cudaEvent_t evFork = nullptr, evJoin = nullptr;
    if (s2 == nullptr) {
        cudaStreamCreateWithFlags(&s2, cudaStreamNonBlocking);
        cudaEventCreateWithFlags(&evFork, cudaEventDisableTiming);
        cudaEventCreateWithFlags(&evJoin, cudaEventDisableTiming);
    }

    // 1. splits (deduped layouts, float4-vectorized)
    split_a_kernel<<<dim3((D / 4 + 255) / 256, B), 256>>>(x, pre_bias, aq, D);
    split_b_kernel<<<dim3((D / 4 + 255) / 256, L), 256>>>(W_enc, bq, D);

    // 2. encode GEMM on tcgen05 (R9 exact)
    cudaFuncSetAttribute(gemm_kernel, cudaFuncAttributeMaxDynamicSharedMemorySize,
                         GEMM_SMEM);
    int ntiles = L >> 8, mtiles = B >> 8;
    gemm_kernel<<<mtiles * ntiles, 160, GEMM_SMEM>>>(aq, bq, latent_bias,
                                                     out_pre, B, L, D);

    // 3. fork: transpose W_dec (fp16) on side stream (starts after gemm)
    cudaEventRecord(evFork, 0);
    cudaStreamWaitEvent(s2, evFork, 0);
    transpose_kernel<<<dim3(L / 32, D / 32), dim3(32, 8), 0, s2>>>(W_dec, wdt, D, L);
    cudaEventRecord(evJoin, s2);

    // 4. topk (fused zero-write) + fp64 boundary refine on main stream
    topk_kernel<<<B, 256>>>(out_pre, kptr, out_lat, tki, tkv, cand, L);
    refine_kernel<<<B, 256>>>(x, pre_bias, W_enc, latent_bias, out_pre, kptr,
                              out_lat, tki, tkv, cand, D, L);

    // 5. join, then sparse decode (fp16 weights)
    cudaStreamWaitEvent(0, evJoin, 0);
    decode_kernel<<<B, 256>>>(pre_bias, tki, tkv, wdt, out_rec, D);
}

// round 13
// speedup vs baseline: 1.3316x; 1.0587x over previous
#include <cuda_runtime.h>
#include <cuda_bf16.h>
#include <cuda_fp16.h>
#include <cstdint>
#include <cstddef>

// tcgen05 is arch-SPECIFIC (sm_103a / sm_100a). The harness also compiles a
// plain compute_103 pass where tcgen05 is illegal, so gate every tcgen05 use.
#if !defined(__CUDA_ARCH__) || defined(__CUDA_ARCH_FEAT_SM103_ALL) || \
    defined(__CUDA_ARCH_FEAT_SM100_ALL) || defined(__CUDA_ARCH_FEAT_SM101_ALL)
#define TC_OK 1
#else
#define TC_OK 0
#endif

// Problem sizes (exact: B=4096, D=4096, L=32768, k=64)
#define BMAX 4096
#define DMAX 4096
#define LMAX 32768
#define K_MAX 512
#define CAND_MAX 128
#define CAPB 2048
#define DELTA 1e-4f

// ---------------------------------------------------------------------------
// Device-global scratch. Deduped splits; wdt fp16.
// ---------------------------------------------------------------------------
__device__ __half         g_wdt[(size_t)LMAX * DMAX];         // W_dec^T fp16 (256MB)
__device__ unsigned short g_aq[(size_t)BMAX * 2 * DMAX];      // [a1,a2] (64MB)
__device__ unsigned short g_bq[(size_t)LMAX * 2 * DMAX];      // [b1,b2] (512MB)
__device__ int   g_tk_idx[(size_t)BMAX * K_MAX];
__device__ float g_tk_val[(size_t)BMAX * K_MAX];
__device__ int   g_cand_idx[(size_t)BMAX * CAND_MAX];
__device__ int   g_nhi[BMAX];
__device__ int   g_ncand[BMAX];

// ---------------------------------------------------------------------------
// PTX helpers
// ---------------------------------------------------------------------------
__device__ __forceinline__ uint32_t smem_u32(const void* p) {
    uint32_t a;
    asm("{ .reg .u64 t; cvta.to.shared.u64 t, %1; cvt.u32.u64 %0, t; }"
        : "=r"(a) : "l"(p));
    return a;
}

#define MBARRIER_INIT(addr, cnt) \
    asm volatile("mbarrier.init.shared.b64 [%0], %1;" :: "r"(addr), "r"(cnt) : "memory")

#define MBARRIER_WAIT_PARITY(addr, par) do {                                   \
    uint32_t _m = (addr); uint32_t _p = (par); uint32_t _d;                    \
    asm volatile("{\n\t.reg .pred p;\n\t"                                      \
        "mbarrier.try_wait.parity.acquire.cta.shared::cta.b64 p, [%1], %2;\n\t"\
        "selp.b32 %0, 1, 0, p;\n\t}"                                           \
        : "=r"(_d) : "r"(_m), "r"(_p) : "memory");                             \
    if (!_d) {                                                                 \
        asm volatile("{\n\t.reg .pred P1;\n\t"                                 \
            "WL_%=:\n\t"                                                       \
            "mbarrier.try_wait.parity.acquire.cta.shared::cta.b64 P1, [%0], %1, 0x989680;\n\t" \
            "@P1 bra.uni WD_%=;\n\t"                                           \
            "bra.uni WL_%=;\n\t"                                               \
            "WD_%=:\n\t}" :: "r"(_m), "r"(_p) : "memory");                     \
    }                                                                          \
} while (0)

// noinc: arrival counts against the init count (default form self-balances
// and can never complete a phase — R4 hang).
#define CPASYNC_ARRIVE_NOINC(addr) \
    asm volatile("cp.async.mbarrier.arrive.noinc.shared::cta.b64 [%0];" \
                 :: "r"(addr) : "memory")

#if TC_OK
#define TCGEN05_ALLOC(sp, n) \
    asm volatile("tcgen05.alloc.cta_group::1.sync.aligned.shared::cta.b32 [%0], %1;" \
                 :: "r"((uint32_t)(sp)), "r"((uint32_t)(n)) : "memory")
#define TCGEN05_DEALLOC(t, n) \
    asm volatile("tcgen05.dealloc.cta_group::1.sync.aligned.b32 %0, %1;" :: "r"(t), "r"(n))
#define TCGEN05_COMMIT(mb) \
    asm volatile("tcgen05.commit.cta_group::1.mbarrier::arrive::one.shared::cluster.b64 [%0];" \
                 :: "r"((uint32_t)(mb)) : "memory")
#define TCGEN05_WAIT_LD() asm volatile("tcgen05.wait::ld.sync.aligned;" ::: "memory")
#define TCGEN05_FENCE_AFTER() asm volatile("tcgen05.fence::after_thread_sync;" ::: "memory")
#define FENCE_PROXY_ASYNC() asm volatile("fence.proxy.async.shared::cta;" ::: "memory")

#define TCGEN05_LD_X32(r, ta) \
    asm volatile("tcgen05.ld.sync.aligned.32x32b.x32.b32 " \
        "{%0,%1,%2,%3,%4,%5,%6,%7,%8,%9,%10,%11,%12,%13,%14,%15," \
        "%16,%17,%18,%19,%20,%21,%22,%23,%24,%25,%26,%27,%28,%29,%30,%31}, [%32];" \
        : "=r"((r)[0]),"=r"((r)[1]),"=r"((r)[2]),"=r"((r)[3]), \
          "=r"((r)[4]),"=r"((r)[5]),"=r"((r)[6]),"=r"((r)[7]), \
          "=r"((r)[8]),"=r"((r)[9]),"=r"((r)[10]),"=r"((r)[11]), \
          "=r"((r)[12]),"=r"((r)[13]),"=r"((r)[14]),"=r"((r)[15]), \
          "=r"((r)[16]),"=r"((r)[17]),"=r"((r)[18]),"=r"((r)[19]), \
          "=r"((r)[20]),"=r"((r)[21]),"=r"((r)[22]),"=r"((r)[23]), \
          "=r"((r)[24]),"=r"((r)[25]),"=r"((r)[26]),"=r"((r)[27]), \
          "=r"((r)[28]),"=r"((r)[29]),"=r"((r)[30]),"=r"((r)[31]) \
        : "r"(ta))

// SW128 K-major smem descriptor (version=1, SBO=64, LBO=1, layout=SW128)
__device__ __forceinline__ uint64_t make_desc(uint32_t addr) {
    const uint64_t base = (uint64_t(2) << 61) | (uint64_t(1) << 46) |
                          (uint64_t(64) << 32) | (uint64_t(1) << 16);
    return base | ((uint64_t)(addr >> 4) & 0x3FFF);
}

__device__ __forceinline__ void mma_f16_ss_cg1(
    uint32_t d, uint64_t adesc, uint64_t bdesc, uint32_t idesc, uint32_t en)
{
    asm volatile("{\n\t.reg .pred p;\n\tsetp.ne.u32 p, %5, 0;\n\t"
        "tcgen05.mma.cta_group::1.kind::f16 [%0], %1, %2, %3, {%4,%4,%4,%4}, p;\n\t}"
        :: "r"(d), "l"(adesc), "l"(bdesc), "r"(idesc), "r"(0u), "r"(en) : "memory");
}
#endif // TC_OK

// ---------------------------------------------------------------------------
// Merged split kernel (float4-vectorized): rows [0,B) -> Aq (x - pb split),
// rows [B, B+L) -> Bq (W_enc split). Deduped [x1,x2] layouts.
// ---------------------------------------------------------------------------
__global__ __launch_bounds__(256) void split_ab_kernel(
    const float* __restrict__ x, const float* __restrict__ pb,
    const float* __restrict__ W,
    unsigned short* __restrict__ Aq, unsigned short* __restrict__ Bq,
    int D, int B)
{
    int d4 = blockIdx.x * 256 + threadIdx.x;
    int r = blockIdx.y;
    if (d4 >= (D >> 2)) return;

    float v[4];
    unsigned short* dst;
    size_t base;
    if (r < B) {
        float4 xv = ((const float4*)(x + (size_t)r * D))[d4];
        float4 pv = ((const float4*)pb)[d4];
        v[0] = xv.x - pv.x; v[1] = xv.y - pv.y;
        v[2] = xv.z - pv.z; v[3] = xv.w - pv.w;
        dst = Aq; base = (size_t)r * 2 * D;
    } else {
        int l = r - B;
        float4 wv = ((const float4*)(W + (size_t)l * D))[d4];
        v[0] = wv.x; v[1] = wv.y; v[2] = wv.z; v[3] = wv.w;
        dst = Bq; base = (size_t)l * 2 * D;
    }

    ushort4 u1, u2;
    unsigned short* p1 = (unsigned short*)&u1;
    unsigned short* p2 = (unsigned short*)&u2;
#pragma unroll
    for (int q = 0; q < 4; q++) {
        __nv_bfloat16 h1 = __float2bfloat16_rn(v[q]);
        __nv_bfloat16 h2 = __float2bfloat16_rn(v[q] - __bfloat162float(h1));
        p1[q] = __bfloat16_as_ushort(h1);
        p2[q] = __bfloat16_as_ushort(h2);
    }
    ((ushort4*)(dst + base))[d4]     = u1;
    ((ushort4*)(dst + base + D))[d4] = u2;
}

// ---------------------------------------------------------------------------
// W_dec [D,L] -> g_wdt [L,D] in fp16
// ---------------------------------------------------------------------------
__global__ __launch_bounds__(256) void transpose_kernel(
    const float* __restrict__ in, __half* __restrict__ out, int D, int L)
{
    __shared__ float tile[32][33];
    int l0 = blockIdx.x * 32, d0 = blockIdx.y * 32;
    int tx = threadIdx.x, ty = threadIdx.y;
#pragma unroll
    for (int i = 0; i < 32; i += 8)
        tile[ty + i][tx] = in[(size_t)(d0 + ty + i) * L + (l0 + tx)];
    __syncthreads();
#pragma unroll
    for (int i = 0; i < 32; i += 8)
        out[(size_t)(l0 + ty + i) * D + (d0 + tx)] = __float2half_rn(tile[tx][ty + i]);
}

// ---------------------------------------------------------------------------
// tcgen05 bf16 GEMM (R9/R12 exact: 256x256 tiles, 3-stage, virtual K=3D)
// ---------------------------------------------------------------------------
#define GSTAGES 3
#define STAGE_BYTES 65536
#define OFF_TMEMPTR 0
#define OFF_FULL    8
#define OFF_EMPTY   32
#define OFF_DONE    56
#define OFF_STAGE   1024
#define GEMM_SMEM   (OFF_STAGE + GSTAGES * STAGE_BYTES)
#define GIDESC ((1u << 4) | (1u << 7) | (1u << 10) | ((256u / 8) << 17) | ((128u / 16) << 24))

__global__ __launch_bounds__(160, 1) void gemm_kernel(
    const unsigned short* __restrict__ Aq, const unsigned short* __restrict__ Bq,
    const float* __restrict__ bias, float* __restrict__ C,
    int M, int N, int D)
{
#if TC_OK
    extern __shared__ char smem[];
    uint32_t sb = smem_u32(smem);
    int tid = threadIdx.x;
    int wid = tid >> 5;

    int mtiles = M >> 8;
    int bid = blockIdx.x;
    int gsz = mtiles * 8;
    int g = bid / gsz, r = bid % gsz;
    int mt = r % mtiles;
    int nt = g * 8 + r / mtiles;
    int m0 = mt << 8, n0 = nt << 8;

    if (tid == 0) {
#pragma unroll
        for (int s = 0; s < GSTAGES; s++) {
            MBARRIER_INIT(sb + OFF_FULL + s * 8, 128);
            MBARRIER_INIT(sb + OFF_EMPTY + s * 8, 1);
        }
        MBARRIER_INIT(sb + OFF_DONE, 1);
    }
    if (wid == 4) TCGEN05_ALLOC(sb + OFF_TMEMPTR, 512);
    __syncthreads();
    uint32_t tmem;
    asm volatile("ld.shared.b32 %0, [%1];" : "=r"(tmem) : "r"(sb + OFF_TMEMPTR));

    const int cpp = D >> 6;
    const int nchunk = 3 * cpp;
    const size_t rowstride = (size_t)(2 * D);

    if (tid < 128) {
        int rrA = tid >> 3, cq = tid & 7;
        for (int it = 0; it < nchunk; it++) {
            int s = it % GSTAGES;
            int wrap = it / GSTAGES;
            if (it >= GSTAGES)
                MBARRIER_WAIT_PARITY(sb + OFF_EMPTY + s * 8, (wrap - 1) & 1);
            int ph = it / cpp, r64 = it % cpp;
            int aoe = ((ph == 2) ? D : 0) + r64 * 64;
            int boe = ((ph == 1) ? D : 0) + r64 * 64;
            uint32_t aoff = sb + OFF_STAGE + s * STAGE_BYTES;
            uint32_t boff = aoff + 32768;
            const unsigned short* gA = Aq + (size_t)m0 * rowstride + aoe + cq * 8;
            const unsigned short* gB = Bq + (size_t)n0 * rowstride + boe + cq * 8;
#pragma unroll
            for (int i = 0; i < 16; i++) {
                int rr = i * 16 + rrA;
                uint32_t off = rr * 128 + cq * 16;
                uint32_t sw = off ^ ((off >> 3) & 0x70);
                asm volatile("cp.async.cg.shared.global [%0], [%1], 16;"
                             :: "r"(aoff + sw), "l"(gA + (size_t)rr * rowstride) : "memory");
            }
#pragma unroll
            for (int i = 0; i < 16; i++) {
                int rr = i * 16 + rrA;
                uint32_t off = rr * 128 + cq * 16;
                uint32_t sw = off ^ ((off >> 3) & 0x70);
                asm volatile("cp.async.cg.shared.global [%0], [%1], 16;"
                             :: "r"(boff + sw), "l"(gB + (size_t)rr * rowstride) : "memory");
            }
            CPASYNC_ARRIVE_NOINC(sb + OFF_FULL + s * 8);
        }
    } else if (tid == 128) {
        for (int it = 0; it < nchunk; it++) {
            int s = it % GSTAGES;
            int wrap = it / GSTAGES;
            MBARRIER_WAIT_PARITY(sb + OFF_FULL + s * 8, wrap & 1);
            FENCE_PROXY_ASYNC();
            uint32_t aoff = sb + OFF_STAGE + s * STAGE_BYTES;
            uint32_t boff = aoff + 32768;
            uint64_t adesc = make_desc(aoff);
            uint64_t bdesc = make_desc(boff);
#pragma unroll
            for (int kk = 0; kk < 4; kk++) {
                uint32_t en = (it == 0 && kk == 0) ? 0u : 1u;
#pragma unroll
                for (int mh = 0; mh < 2; mh++) {
                    mma_f16_ss_cg1(tmem + mh * 256,
                                   adesc + mh * 1024 + kk * 2,
                                   bdesc + kk * 2, GIDESC, en);
                }
            }
            TCGEN05_COMMIT(sb + OFF_EMPTY + s * 8);
        }
        TCGEN05_COMMIT(sb + OFF_DONE);
    }

    if (tid < 128) {
        MBARRIER_WAIT_PARITY(sb + OFF_DONE, 0);
        TCGEN05_FENCE_AFTER();
        int w = wid, lid = tid & 31;
        float* ebuf = (float*)(smem + OFF_STAGE) + w * (32 * 33);
        uint32_t woff = ((uint32_t)w) << 21;
#pragma unroll
        for (int mh = 0; mh < 2; mh++) {
            for (int cb = 0; cb < 8; cb++) {
                uint32_t regs[32];
                TCGEN05_LD_X32(regs, tmem + mh * 256 + cb * 32 + woff);
                TCGEN05_WAIT_LD();
#pragma unroll
                for (int j = 0; j < 32; j++) ebuf[lid * 33 + j] = __uint_as_float(regs[j]);
                __syncwarp();
                float bv = bias[n0 + cb * 32 + lid];
                int rbase = m0 + mh * 128 + w * 32;
#pragma unroll
                for (int rr = 0; rr < 32; rr++) {
                    C[(size_t)(rbase + rr) * N + n0 + cb * 32 + lid] =
                        ebuf[rr * 33 + lid] + bv;
                }
                __syncwarp();
            }
        }
    }
    __syncthreads();
    if (wid == 4) TCGEN05_DEALLOC(tmem, 512);
#endif // TC_OK
}

// ---------------------------------------------------------------------------
// TopK v2.1: 2-pass, float4 loads, fused latents zero-write (R12 exact)
// ---------------------------------------------------------------------------
__device__ __forceinline__ unsigned ord_key(float v) {
    unsigned u = __float_as_uint(v);
    return (u & 0x80000000u) ? ~u : (u | 0x80000000u);
}

__global__ __launch_bounds__(256) void topk_kernel(
    const float* __restrict__ pre, const int* __restrict__ kptr,
    float* __restrict__ latents, int* __restrict__ tki, float* __restrict__ tkv,
    int* __restrict__ cand, int L)
{
    __shared__ int   hist[CAPB];
    __shared__ int   segsum[256];
    __shared__ float s_cv[CAPB];
    __shared__ int   s_ci[CAPB];
    __shared__ int   s_bin, s_c1, s_nbin, s_nhi, s_nc;
    __shared__ unsigned s_vkkey;

    int tid = threadIdx.x;
    int row = blockIdx.x;
    const float4* p4 = (const float4*)(pre + (size_t)row * L);
    float4* lat4 = (float4*)(latents + (size_t)row * L);
    int L4 = L >> 2;

    int k = *kptr;
    if (k > K_MAX) k = K_MAX;
    if (k > L)     k = L;
    if (k <= 0) {
        float4 z = make_float4(0.f, 0.f, 0.f, 0.f);
        for (int i = tid; i < L4; i += 256) lat4[i] = z;
        if (tid == 0) { g_nhi[row] = 0; g_ncand[row] = 0; }
        return;
    }

#pragma unroll
    for (int j = tid; j < CAPB; j += 256) hist[j] = 0;
    __syncthreads();
    for (int i = tid; i < L4; i += 256) {
        float4 v4 = p4[i];
        atomicAdd(&hist[ord_key(v4.x) >> 21], 1);
        atomicAdd(&hist[ord_key(v4.y) >> 21], 1);
        atomicAdd(&hist[ord_key(v4.z) >> 21], 1);
        atomicAdd(&hist[ord_key(v4.w) >> 21], 1);
    }
    __syncthreads();

    {
        int base = tid * 8, s = 0;
#pragma unroll
        for (int j = 0; j < 8; j++) s += hist[base + j];
        segsum[tid] = s;
        __syncthreads();
        for (int off = 1; off < 256; off <<= 1) {
            int v = (tid + off < 256) ? segsum[tid + off] : 0;
            __syncthreads();
            segsum[tid] += v;
            __syncthreads();
        }
        int nxt = (tid < 255) ? segsum[tid + 1] : 0;
        if (nxt < k && segsum[tid] >= k) {
            int running = nxt;
#pragma unroll
            for (int j = 7; j >= 0; j--) {
                int c = hist[base + j];
                if (running < k && running + c >= k) { s_bin = base + j; s_c1 = running; }
                running += c;
            }
        }
    }
    if (tid == 0) { s_nbin = 0; s_nhi = 0; s_nc = 0; }
    __syncthreads();
    int binb = s_bin, c1 = s_c1;
    int rem = k - c1;

    for (int i = tid; i < L4; i += 256) {
        float4 v4 = p4[i];
        float vv[4] = {v4.x, v4.y, v4.z, v4.w};
        float ov[4];
#pragma unroll
        for (int q = 0; q < 4; q++) {
            float v = vv[q];
            int u11 = (int)(ord_key(v) >> 21);
            float rv = v > 0.f ? v : 0.f;
            if (u11 > binb) {
                ov[q] = rv;
                int slot = atomicAdd(&s_nhi, 1);
                if (slot < K_MAX) {
                    tki[(size_t)row * K_MAX + slot] = i * 4 + q;
                    tkv[(size_t)row * K_MAX + slot] = rv;
                }
            } else {
                ov[q] = 0.f;
                if (u11 == binb) {
                    int c = atomicAdd(&s_nbin, 1);
                    if (c < CAPB) { s_cv[c] = v; s_ci[c] = i * 4 + q; }
                }
            }
        }
        lat4[i] = make_float4(ov[0], ov[1], ov[2], ov[3]);
    }
    __syncthreads();
    int nbin = s_nbin < CAPB ? s_nbin : CAPB;
    if (rem > nbin) rem = nbin;

    for (int j = tid; j < nbin; j += 256) {
        unsigned kj = ord_key(s_cv[j]);
        int cgt = 0, ceq = 0;
        for (int i = 0; i < nbin; i++) {
            unsigned ki = ord_key(s_cv[i]);
            cgt += (ki > kj);
            ceq += (ki == kj);
        }
        if (cgt <= rem - 1 && rem - 1 < cgt + ceq) s_vkkey = kj;
    }
    __syncthreads();

    float v_k;
    {
        unsigned kk2 = s_vkkey;
        unsigned u = (kk2 & 0x80000000u) ? (kk2 & 0x7fffffffu) : ~kk2;
        v_k = __uint_as_float(u);
    }
    float w_hi = v_k + DELTA, w_lo = v_k - DELTA;

    for (int j = tid; j < nbin; j += 256) {
        float v = s_cv[j];
        if (v > w_hi) {
            int slot = atomicAdd(&s_nhi, 1);
            if (slot < K_MAX) {
                float rv = v > 0.f ? v : 0.f;
                latents[(size_t)row * L + s_ci[j]] = rv;
                tki[(size_t)row * K_MAX + slot] = s_ci[j];
                tkv[(size_t)row * K_MAX + slot] = rv;
            }
        } else if (v > w_lo) {
            int c = atomicAdd(&s_nc, 1);
            if (c < CAND_MAX)
                cand[(size_t)row * CAND_MAX + c] = s_ci[j];
        }
    }
    __syncthreads();
    if (tid == 0) {
        g_nhi[row]   = s_nhi < K_MAX ? s_nhi : K_MAX;
        g_ncand[row] = s_nc < CAND_MAX ? s_nc : CAND_MAX;
    }
}

// ---------------------------------------------------------------------------
// Fused refine + decode: per row, resolve boundary candidates (fp64 dots for
// ambiguous rows, xc recomputed inline), scatter winners, then decode with
// fp16 weights. __syncthreads makes thread-0's global writes block-visible.
// ---------------------------------------------------------------------------
__global__ __launch_bounds__(256) void findecode_kernel(
    const float* __restrict__ x, const float* __restrict__ pb,
    const float* __restrict__ W, const float* __restrict__ lb,
    const float* __restrict__ pre, const int* __restrict__ kptr,
    float* __restrict__ latents, int* __restrict__ tki, float* __restrict__ tkv,
    const int* __restrict__ cand, const __half* __restrict__ wdt,
    float* __restrict__ out, int D, int L)
{
    __shared__ double s_val[CAND_MAX];
    __shared__ double s_red[8];
    __shared__ unsigned char s_win[CAND_MAX];
    __shared__ int s_nsel;
    __shared__ int   sidx[K_MAX];
    __shared__ float sval[K_MAX];

    int row = blockIdx.x, tid = threadIdx.x;
    int k = *kptr;
    if (k > K_MAX) k = K_MAX;
    if (k > L)     k = L;

    int nhi = 0, nc = 0, m = 0;
    if (k > 0) {
        nhi = g_nhi[row];
        nc  = g_ncand[row];
        m = k - nhi;
        if (m < 0) m = 0;
        if (m > nc) m = nc;

        if (nc > m) {
            // ambiguous: exact fp64 ranking of window candidates
            for (int j = 0; j < nc; j++) {
                int idx = cand[(size_t)row * CAND_MAX + j];
                const float* xr = x + (size_t)row * D;
                const float* wr = W + (size_t)idx * D;
                double part = 0.0;
                for (int t = tid; t < D; t += 256) {
                    float xct = xr[t] - pb[t];
                    part += (double)xct * (double)wr[t];
                }
#pragma unroll
                for (int off = 16; off > 0; off >>= 1)
                    part += __shfl_down_sync(0xFFFFFFFFu, part, off);
                if ((tid & 31) == 0) s_red[tid >> 5] = part;
                __syncthreads();
                if (tid == 0) {
                    double tot = 0.0;
#pragma unroll
                    for (int w = 0; w < 8; w++) tot += s_red[w];
                    s_val[j] = tot + (double)lb[idx];
                }
                __syncthreads();
            }
            if (tid == 0) {
                for (int j = 0; j < nc; j++) s_win[j] = 0;
                for (int s = 0; s < m; s++) {
                    int best = -1; double bv = -1e300;
                    for (int j = 0; j < nc; j++)
                        if (!s_win[j] && s_val[j] > bv) { bv = s_val[j]; best = j; }
                    if (best >= 0) s_win[best] = 1;
                }
            }
            __syncthreads();
        } else {
            if (tid < CAND_MAX) s_win[tid] = (tid < nc) ? 1 : 0;
            __syncthreads();
        }

        if (tid == 0) {
            int slot = nhi;
            for (int j = 0; j < nc && slot < k; j++) {
                if (s_win[j]) {
                    int idx = cand[(size_t)row * CAND_MAX + j];
                    float v = pre[(size_t)row * L + idx];
                    float rv = v > 0.f ? v : 0.f;
                    latents[(size_t)row * L + idx] = rv;
                    tki[(size_t)row * K_MAX + slot] = idx;
                    tkv[(size_t)row * K_MAX + slot] = rv;
                    slot++;
                }
            }
            s_nsel = slot;
        }
    } else {
        if (tid == 0) s_nsel = 0;
    }
    __syncthreads();            // makes thread-0 global tki/tkv writes visible

    // ---- decode ----
    int kk = s_nsel;
    if (kk > K_MAX) kk = K_MAX;
    for (int i = tid; i < kk; i += 256) {
        sidx[i] = tki[(size_t)row * K_MAX + i];
        sval[i] = tkv[(size_t)row * K_MAX + i];
    }
    __syncthreads();

    const int nc2 = D >> 9;
    const float2* pb2 = (const float2*)pb;
    float2 acc[8];
#pragma unroll
    for (int c = 0; c < 8; c++) {
        if (c < nc2) acc[c] = pb2[c * 256 + tid];
        else acc[c] = make_float2(0.f, 0.f);
    }

    for (int j = 0; j < kk; j++) {
        float v = sval[j];
        const __half2* w2 = (const __half2*)(wdt + (size_t)sidx[j] * D);
#pragma unroll
        for (int c = 0; c < 8; c++) {
            if (c < nc2) {
                float2 wf = __half22float2(w2[c * 256 + tid]);
                acc[c].x += v * wf.x;
                acc[c].y += v * wf.y;
            }
        }
    }

    float2* o2 = (float2*)(out + (size_t)row * D);
#pragma unroll
    for (int c = 0; c < 8; c++)
        if (c < nc2) o2[c * 256 + tid] = acc[c];
}

// ---------------------------------------------------------------------------
// Launch — splits -> GEMM (alone) -> fork transpose on side stream ->
// topk -> join -> fused refine+decode.
// ---------------------------------------------------------------------------
extern "C" void kernel_launch(void* const* d_in, const int* in_sizes, int n_in,
                              void* d_out, int out_size)
{
    const float* x           = (const float*)d_in[0];
    const float* W_enc       = (const float*)d_in[1];
    const float* latent_bias = (const float*)d_in[2];
    const float* pre_bias    = (const float*)d_in[3];
    const float* W_dec       = (const float*)d_in[4];
    const int*   kptr        = (const int*)d_in[5];

    int L = in_sizes[2];
    int D = in_sizes[3];
    int B = in_sizes[0] / D;

    float* out_pre = (float*)d_out;
    float* out_lat = out_pre + (size_t)B * L;
    float* out_rec = out_lat + (size_t)B * L;

    float *tkv;
    __half* wdt;
    int *tki, *cand;
    unsigned short *aq, *bq;
    cudaGetSymbolAddress((void**)&wdt,  g_wdt);
    cudaGetSymbolAddress((void**)&tki,  g_tk_idx);
    cudaGetSymbolAddress((void**)&tkv,  g_tk_val);
    cudaGetSymbolAddress((void**)&cand, g_cand_idx);
    cudaGetSymbolAddress((void**)&aq,   g_aq);
    cudaGetSymbolAddress((void**)&bq,   g_bq);

    static cudaStream_t s2 = nullptr;
    static cudaEvent_t evFork = nullptr, evJoin = nullptr;
    if (s2 == nullptr) {
        cudaStreamCreateWithFlags(&s2, cudaStreamNonBlocking);
        cudaEventCreateWithFlags(&evFork, cudaEventDisableTiming);
        cudaEventCreateWithFlags(&evJoin, cudaEventDisableTiming);
    }

    // 1. merged splits (deduped layouts, float4-vectorized)
    split_ab_kernel<<<dim3((D / 4 + 255) / 256, B + L), 256>>>(
        x, pre_bias, W_enc, aq, bq, D, B);

    // 2. encode GEMM on tcgen05 (owns L2 — runs alone)
    cudaFuncSetAttribute(gemm_kernel, cudaFuncAttributeMaxDynamicSharedMemorySize,
                         GEMM_SMEM);
    int ntiles = L >> 8, mtiles = B >> 8;
    gemm_kernel<<<mtiles * ntiles, 160, GEMM_SMEM>>>(aq, bq, latent_bias,
                                                     out_pre, B, L, D);

    // 3. fork: transpose W_dec (fp16) on side stream (starts after gemm)
    cudaEventRecord(evFork, 0);
    cudaStreamWaitEvent(s2, evFork, 0);
    transpose_kernel<<<dim3(L / 32, D / 32), dim3(32, 8), 0, s2>>>(W_dec, wdt, D, L);
    cudaEventRecord(evJoin, s2);

    // 4. topk (fused zero-write) on main stream
    topk_kernel<<<B, 256>>>(out_pre, kptr, out_lat, tki, tkv, cand, L);

    // 5. join transpose, then fused refine+decode
    cudaStreamWaitEvent(0, evJoin, 0);
    findecode_kernel<<<B, 256>>>(x, pre_bias, W_enc, latent_bias, out_pre, kptr,
                                 out_lat, tki, tkv, cand, wdt, out_rec, D, L);
}